// round 3
// baseline (speedup 1.0000x reference)
#include <cuda_runtime.h>
#include <cuda_bf16.h>
#include <stdint.h>

// Problem constants
constexpr int kB  = 32;
constexpr int kL  = 128;
constexpr int kD  = 300;
constexpr int kH  = 1024;
constexpr int kH3 = 3 * kH;   // 3072
constexpr int kH4 = 4 * kH;   // 4096
constexpr int kH6 = 6 * kH;   // 6144
constexpr int MAXM = 2048;    // max nodes in one tree level (<= B * L/2)

#define REF_NONE  (-1)
#define REF_LEAF  0x40000000

// ---------------- device scratch (static, no allocations) ----------------
__device__ float g_X[(size_t)kB * kL * kH4];      // 64 MB: emb @ W_ih^T + b_ih + b_hh
__device__ float g_hs[(size_t)kB * kL * kH];      // 16 MB leaf h
__device__ float g_cs[(size_t)kB * kL * kH];      // 16 MB leaf c
__device__ float g_nodeh[(size_t)kB * 128 * kH];  // internal node h
__device__ float g_nodec[(size_t)kB * 128 * kH];  // internal node c
__device__ float g_compIn[(size_t)MAXM * kH3];    // gathered [h_l|h_x|h_r]
__device__ float g_gates[(size_t)MAXM * kH6];     // GEMM outputs (shared LSTM/compose)

__device__ int g_nodeL[kB * 128];
__device__ int g_nodeR[kB * 128];
__device__ int g_nodeX[kB * 128];
__device__ int g_nodeLvl[kB * 128];
__device__ int g_nNodes[kB];
__device__ int g_root[kB];
__device__ int g_lvlList[kB * 128];               // (b<<8)|node
__device__ int g_lvlOff[132];
__device__ int g_maxLvl;

__device__ unsigned g_barCount = 0;
__device__ unsigned g_barGen   = 0;

// ---------------- helpers ----------------
__device__ __forceinline__ float sigm(float x) { return 1.0f / (1.0f + expf(-x)); }

__device__ __forceinline__ void gridBarrier(unsigned &gen) {
    __syncthreads();
    if (threadIdx.x == 0) {
        __threadfence();
        unsigned nb = gridDim.x;
        if (atomicAdd(&g_barCount, 1u) == nb - 1u) {
            g_barCount = 0;
            __threadfence();
            atomicExch(&g_barGen, gen + 1u);
        } else {
            while (*((volatile unsigned *)&g_barGen) < gen + 1u) __nanosleep(64);
        }
    }
    gen++;
    __syncthreads();
}

__device__ __forceinline__ float h_of(int ref, int b, int jj) {
    if (ref < 0) return 0.0f;
    if (ref & REF_LEAF) {
        int pos = ref & 0xFFFF;
        return __ldcg(&g_hs[((size_t)(b * kL + pos)) * kH + jj]);
    }
    return __ldcg(&g_nodeh[((size_t)(b * 128 + ref)) * kH + jj]);
}
__device__ __forceinline__ float c_of(int ref, int b, int jj) {
    if (ref < 0) return 0.0f;
    if (ref & REF_LEAF) {
        int pos = ref & 0xFFFF;
        return __ldcg(&g_cs[((size_t)(b * kL + pos)) * kH + jj]);
    }
    return __ldcg(&g_nodec[((size_t)(b * 128 + ref)) * kH + jj]);
}

// ---------------- generic tiled f32 GEMM: C[M,N] = A(MxK) @ B(NxK)^T (+bias) ----
// 256 threads, (BM/TM)x(BN/TN) must be 16x16. Grid-stride over tiles.
// A loads use __ldcg (cross-block producer), B via __ldg, C stores via __stcg.
template <int BM, int BN, int BK, int TM, int TN>
__device__ void gemmNT(const float *__restrict__ A, int lda, int M,
                       const float *__restrict__ Bm, int ldb,
                       int N, int K,
                       float *__restrict__ C, int ldc,
                       const float *__restrict__ bias1,
                       const float *__restrict__ bias2,
                       float *smem) {
    const int tid = threadIdx.x;
    const int ty = tid >> 4, tx = tid & 15;
    float *As = smem;                       // [BK][BM+4]
    float *Bs = smem + BK * (BM + 4);       // [BK][BN+4]
    const int tilesM = (M + BM - 1) / BM;
    const int tilesN = N / BN;
    for (int t = blockIdx.x; t < tilesM * tilesN; t += gridDim.x) {
        const int tm = t % tilesM, tn = t / tilesM;
        const int m0 = tm * BM, n0 = tn * BN;
        float acc[TM][TN];
#pragma unroll
        for (int i = 0; i < TM; i++)
#pragma unroll
            for (int j = 0; j < TN; j++) acc[i][j] = 0.0f;
        for (int k0 = 0; k0 < K; k0 += BK) {
#pragma unroll
            for (int idx = tid; idx < BM * BK; idx += 256) {
                int m = idx / BK, kk = idx - m * BK;
                int row = m0 + m, k = k0 + kk;
                float v = 0.0f;
                if (row < M && k < K) v = __ldcg(A + (size_t)row * lda + k);
                As[kk * (BM + 4) + m] = v;
            }
#pragma unroll
            for (int idx = tid; idx < BN * BK; idx += 256) {
                int n = idx / BK, kk = idx - n * BK;
                int k = k0 + kk;
                float v = 0.0f;
                if (k < K) v = __ldg(Bm + (size_t)(n0 + n) * ldb + k);
                Bs[kk * (BN + 4) + n] = v;
            }
            __syncthreads();
#pragma unroll
            for (int kk = 0; kk < BK; kk++) {
                float a[TM], bb[TN];
#pragma unroll
                for (int i = 0; i < TM; i++) a[i] = As[kk * (BM + 4) + ty * TM + i];
#pragma unroll
                for (int j = 0; j < TN; j++) bb[j] = Bs[kk * (BN + 4) + tx * TN + j];
#pragma unroll
                for (int i = 0; i < TM; i++)
#pragma unroll
                    for (int j = 0; j < TN; j++) acc[i][j] = fmaf(a[i], bb[j], acc[i][j]);
            }
            __syncthreads();
        }
#pragma unroll
        for (int i = 0; i < TM; i++) {
            int row = m0 + ty * TM + i;
            if (row < M) {
#pragma unroll
                for (int j = 0; j < TN; j++) {
                    int col = n0 + tx * TN + j;
                    float v = acc[i][j];
                    if (bias1) v += __ldg(bias1 + col);
                    if (bias2) v += __ldg(bias2 + col);
                    __stcg(C + (size_t)row * ldc + col, v);
                }
            }
        }
    }
}

// ---------------- tree structure kernel (1 block, 32 threads) ----------------
__global__ void tree_kernel(const int *__restrict__ words, const int *__restrict__ length) {
    int b = threadIdx.x;
    if (b < kB) {
        int df[kL];
        for (int l = 0; l < kL; l++) df[l] = words[b * kL + l] % 1000;
        int n = length[b];
        short ss[kL], se[kL], spos[kL];
        signed char sst[kL];
        int sleft[kL];
        int lvl[kL];
        int nn = 0;
        int root;
        if (n <= 0) {
            root = REF_NONE;
        } else if (n == 1) {
            root = REF_LEAF | 0;
        } else {
            int sp = 0;
            ss[0] = 0; se[0] = (short)n; sst[0] = 0; sp = 1;
            int ret = 0;
            bool returning = false;
            while (sp > 0) {
                int top = sp - 1;
                if (returning) {
                    if (sst[top] == 1) {
                        sleft[top] = ret; sst[top] = 2; returning = false;
                    } else {  // stage 3: ret is the right child -> complete node
                        int Lr = sleft[top], Rr = ret, x = spos[top];
                        int ll = (Lr >= 0 && !(Lr & REF_LEAF)) ? lvl[Lr] : 0;
                        int rl = (Rr >= 0 && !(Rr & REF_LEAF)) ? lvl[Rr] : 0;
                        lvl[nn] = 1 + (ll > rl ? ll : rl);
                        g_nodeL[b * 128 + nn] = Lr;
                        g_nodeR[b * 128 + nn] = Rr;
                        g_nodeX[b * 128 + nn] = x;
                        g_nodeLvl[b * 128 + nn] = lvl[nn];
                        ret = nn; nn++; sp--;
                        continue;  // still returning
                    }
                }
                if (sst[top] == 0) {
                    int s = ss[top], e = se[top];
                    int best = df[s], bp = s;
                    for (int k = s + 1; k < e; k++)
                        if (df[k] < best) { best = df[k]; bp = k; }  // first min == argmax score
                    spos[top] = (short)bp;
                    if (bp == s)        { sleft[top] = REF_NONE;     sst[top] = 2; }
                    else if (bp == s + 1) { sleft[top] = REF_LEAF | s; sst[top] = 2; }
                    else {
                        sst[top] = 1;
                        ss[sp] = (short)s; se[sp] = (short)bp; sst[sp] = 0; sp++;
                        continue;
                    }
                }
                if (sst[top] == 2) {
                    int rs = spos[top] + 1, e = se[top];
                    int Rr;
                    if (rs == e)          Rr = REF_NONE;
                    else if (rs + 1 == e) Rr = REF_LEAF | rs;
                    else {
                        sst[top] = 3;
                        ss[sp] = (short)rs; se[sp] = (short)e; sst[sp] = 0; sp++;
                        continue;
                    }
                    int Lr = sleft[top], x = spos[top];
                    int ll = (Lr >= 0 && !(Lr & REF_LEAF)) ? lvl[Lr] : 0;
                    int rl = (Rr >= 0 && !(Rr & REF_LEAF)) ? lvl[Rr] : 0;
                    lvl[nn] = 1 + (ll > rl ? ll : rl);
                    g_nodeL[b * 128 + nn] = Lr;
                    g_nodeR[b * 128 + nn] = Rr;
                    g_nodeX[b * 128 + nn] = x;
                    g_nodeLvl[b * 128 + nn] = lvl[nn];
                    ret = nn; nn++; sp--;
                    returning = true;
                }
            }
            root = ret;
        }
        g_root[b] = root;
        g_nNodes[b] = nn;
    }
    __syncthreads();
    if (threadIdx.x == 0) {
        int cnt[130];
        for (int i = 0; i < 130; i++) cnt[i] = 0;
        int mx = 0;
        for (int bb = 0; bb < kB; bb++) {
            int nn = g_nNodes[bb];
            for (int i = 0; i < nn; i++) {
                int lv = g_nodeLvl[bb * 128 + i];
                cnt[lv]++;
                if (lv > mx) mx = lv;
            }
        }
        int run = 0;
        for (int lv = 1; lv <= mx; lv++) { g_lvlOff[lv] = run; run += cnt[lv]; }
        g_lvlOff[mx + 1] = run;
        int pos[130];
        for (int lv = 1; lv <= mx; lv++) pos[lv] = g_lvlOff[lv];
        for (int bb = 0; bb < kB; bb++) {
            int nn = g_nNodes[bb];
            for (int i = 0; i < nn; i++) {
                int lv = g_nodeLvl[bb * 128 + i];
                g_lvlList[pos[lv]++] = (bb << 8) | i;
            }
        }
        g_maxLvl = mx;
    }
}

// ---------------- X precompute: g_X = emb @ W_ih^T + b_ih + b_hh ----------------
__global__ __launch_bounds__(256) void x_kernel(const float *__restrict__ emb,
                                                const float *__restrict__ Wih,
                                                const float *__restrict__ bih,
                                                const float *__restrict__ bhh) {
    __shared__ float smem[16 * 68 + 16 * 132];  // 3200 floats
    gemmNT<64, 128, 16, 4, 8>(emb, kD, kB * kL, Wih, kD, kH4, kD,
                              g_X, kH4, bih, bhh, smem);
}

// ---------------- persistent kernel: LSTM recurrence + tree compose + output ----
__global__ __launch_bounds__(256) void main_kernel(const float *__restrict__ Whh,
                                                   const float *__restrict__ Wcomp,
                                                   const float *__restrict__ bcomp,
                                                   float *__restrict__ out) {
    __shared__ float smem[16 * 68 + 16 * 132];  // big enough for both GEMM configs
    unsigned gen = *((volatile unsigned *)&g_barGen);
    const int tid = threadIdx.x;
    const int gsz = gridDim.x * 256;
    const int gtid = blockIdx.x * 256 + tid;

    // ---- LSTM t = 0 (h_prev = c_prev = 0; gates come only from X) ----
    for (int idx = gtid; idx < kB * kH; idx += gsz) {
        int b = idx >> 10, j = idx & 1023;
        const float *Xr = g_X + (size_t)(b * kL) * kH4;
        float gi = Xr[j], gf = Xr[kH + j], gg = Xr[2 * kH + j], go = Xr[3 * kH + j];
        (void)gf;  // c_prev = 0, forget term vanishes
        float c = sigm(gi) * tanhf(gg);
        float h = sigm(go) * tanhf(c);
        __stcg(&g_cs[(size_t)(b * kL) * kH + j], c);
        __stcg(&g_hs[(size_t)(b * kL) * kH + j], h);
    }
    gridBarrier(gen);

    // ---- LSTM t = 1..127 ----
    for (int t = 1; t < kL; t++) {
        gemmNT<32, 32, 32, 2, 2>(g_hs + (size_t)(t - 1) * kH, kL * kH, kB,
                                 Whh, kH, kH4, kH,
                                 g_gates, kH4, nullptr, nullptr, smem);
        gridBarrier(gen);
        for (int idx = gtid; idx < kB * kH; idx += gsz) {
            int b = idx >> 10, j = idx & 1023;
            const float *Xr = g_X + (size_t)(b * kL + t) * kH4;
            const float *Gr = g_gates + (size_t)b * kH4;
            float gi = __ldcg(Gr + j)          + Xr[j];
            float gf = __ldcg(Gr + kH + j)     + Xr[kH + j];
            float gg = __ldcg(Gr + 2 * kH + j) + Xr[2 * kH + j];
            float go = __ldcg(Gr + 3 * kH + j) + Xr[3 * kH + j];
            float cp = __ldcg(&g_cs[(size_t)(b * kL + t - 1) * kH + j]);
            float c = sigm(gf) * cp + sigm(gi) * tanhf(gg);
            float h = sigm(go) * tanhf(c);
            __stcg(&g_cs[(size_t)(b * kL + t) * kH + j], c);
            __stcg(&g_hs[(size_t)(b * kL + t) * kH + j], h);
        }
        gridBarrier(gen);
    }

    // ---- compose, level by level ----
    const int maxLvl = g_maxLvl;
    for (int lvl = 1; lvl <= maxLvl; lvl++) {
        const int off = g_lvlOff[lvl];
        const int cnt = g_lvlOff[lvl + 1] - off;

        // gather concat[h_l, h_x, h_r] into g_compIn
        for (int idx = gtid; idx < cnt * kH3; idx += gsz) {
            int i = idx / kH3, q = idx - i * kH3;
            int e = g_lvlList[off + i];
            int b = e >> 8, nd = e & 255;
            int seg = q >> 10, jj = q & 1023;
            float v;
            if (seg == 1) {
                int x = g_nodeX[b * 128 + nd];
                v = __ldcg(&g_hs[(size_t)(b * kL + x) * kH + jj]);
            } else {
                int r = (seg == 0) ? g_nodeL[b * 128 + nd] : g_nodeR[b * 128 + nd];
                v = h_of(r, b, jj);
            }
            __stcg(&g_compIn[(size_t)i * kH3 + q], v);
        }
        gridBarrier(gen);

        // batched GEMM: gates = compIn @ W_comp^T
        gemmNT<64, 128, 16, 4, 8>(g_compIn, kH3, cnt, Wcomp, kH3, kH6, kH3,
                                  g_gates, kH6, nullptr, nullptr, smem);
        gridBarrier(gen);

        // epilogue: gate nonlinearity + cell update
        for (int idx = gtid; idx < cnt * kH; idx += gsz) {
            int i = idx >> 10, jj = idx & 1023;
            int e = g_lvlList[off + i];
            int b = e >> 8, nd = e & 255;
            const float *g = g_gates + (size_t)i * kH6;
            float ai  = __ldcg(g + jj)            + __ldg(bcomp + jj);
            float afl = __ldcg(g + kH + jj)       + __ldg(bcomp + kH + jj);
            float afx = __ldcg(g + 2 * kH + jj)   + __ldg(bcomp + 2 * kH + jj);
            float afr = __ldcg(g + 3 * kH + jj)   + __ldg(bcomp + 3 * kH + jj);
            float au  = __ldcg(g + 4 * kH + jj)   + __ldg(bcomp + 4 * kH + jj);
            float ao  = __ldcg(g + 5 * kH + jj)   + __ldg(bcomp + 5 * kH + jj);
            int rl = g_nodeL[b * 128 + nd];
            int rr = g_nodeR[b * 128 + nd];
            int x  = g_nodeX[b * 128 + nd];
            float cl = c_of(rl, b, jj);
            float cr = c_of(rr, b, jj);
            float cx = __ldcg(&g_cs[(size_t)(b * kL + x) * kH + jj]);
            float c = sigm(ai) * tanhf(au) + sigm(afl) * cl + sigm(afx) * cx + sigm(afr) * cr;
            float h = sigm(ao) * tanhf(c);
            __stcg(&g_nodeh[(size_t)(b * 128 + nd) * kH + jj], h);
            __stcg(&g_nodec[(size_t)(b * 128 + nd) * kH + jj], c);
        }
        gridBarrier(gen);
    }

    // ---- output: h then c of each batch root ----
    for (int idx = gtid; idx < kB * kH; idx += gsz) {
        int b = idx >> 10, jj = idx & 1023;
        int r = g_root[b];
        out[idx]           = h_of(r, b, jj);
        out[kB * kH + idx] = c_of(r, b, jj);
    }
}

// ---------------- launch ----------------
extern "C" void kernel_launch(void *const *d_in, const int *in_sizes, int n_in,
                              void *d_out, int out_size) {
    (void)in_sizes; (void)n_in; (void)out_size;
    const float *emb   = (const float *)d_in[0];
    const float *Wih   = (const float *)d_in[1];
    const float *Whh   = (const float *)d_in[2];
    const float *bih   = (const float *)d_in[3];
    const float *bhh   = (const float *)d_in[4];
    const float *Wcomp = (const float *)d_in[5];
    const float *bcomp = (const float *)d_in[6];
    const int *words   = (const int *)d_in[7];
    const int *len     = (const int *)d_in[8];
    float *out = (float *)d_out;

    tree_kernel<<<1, 32>>>(words, len);
    x_kernel<<<2048, 256>>>(emb, Wih, bih, bhh);
    main_kernel<<<148, 256>>>(Whh, Wcomp, bcomp, out);
}

// round 5
// speedup vs baseline: 1.0805x; 1.0805x over previous
#include <cuda_runtime.h>
#include <cuda_bf16.h>
#include <stdint.h>

// Problem constants
constexpr int kB  = 32;
constexpr int kL  = 128;
constexpr int kD  = 300;
constexpr int kH  = 1024;
constexpr int kH3 = 3 * kH;   // 3072
constexpr int kH4 = 4 * kH;   // 4096
constexpr int kH6 = 6 * kH;   // 6144
constexpr int MAXM = 2048;    // max nodes in one tree level (<= B * L/2)

#define REF_NONE  (-1)
#define REF_LEAF  0x40000000

// ---------------- device scratch (static, no allocations) ----------------
__device__ float g_X[(size_t)kB * kL * kH4];      // 64 MB: emb @ W_ih^T + b_ih + b_hh
__device__ float g_hs[(size_t)kB * kL * kH];      // 16 MB leaf h
__device__ float g_cs[(size_t)kB * kL * kH];      // 16 MB leaf c
__device__ float g_nodeh[(size_t)kB * 128 * kH];  // internal node h
__device__ float g_nodec[(size_t)kB * 128 * kH];  // internal node c
__device__ float g_compIn[(size_t)MAXM * kH3];    // gathered [h_l|h_x|h_r]
__device__ float g_gates[(size_t)MAXM * kH6];     // GEMM outputs (shared LSTM/compose)

__device__ int g_nodeL[kB * 128];
__device__ int g_nodeR[kB * 128];
__device__ int g_nodeX[kB * 128];
__device__ int g_nodeLvl[kB * 128];
__device__ int g_nNodes[kB];
__device__ int g_root[kB];
__device__ int g_lvlList[kB * 128];               // (b<<8)|node
__device__ int g_lvlOff[132];
__device__ int g_maxLvl;

__device__ unsigned g_barCount = 0;
__device__ unsigned g_barGen   = 0;

// ---------------- helpers ----------------
__device__ __forceinline__ float sigm(float x) { return 1.0f / (1.0f + expf(-x)); }

__device__ __forceinline__ void gridBarrier(unsigned &gen) {
    __syncthreads();
    if (threadIdx.x == 0) {
        __threadfence();
        unsigned nb = gridDim.x;
        if (atomicAdd(&g_barCount, 1u) == nb - 1u) {
            g_barCount = 0;
            __threadfence();
            atomicExch(&g_barGen, gen + 1u);
        } else {
            while (*((volatile unsigned *)&g_barGen) < gen + 1u) __nanosleep(64);
        }
    }
    gen++;
    __syncthreads();
}

__device__ __forceinline__ float h_of(int ref, int b, int jj) {
    if (ref < 0) return 0.0f;
    if (ref & REF_LEAF) {
        int pos = ref & 0xFFFF;
        return __ldcg(&g_hs[((size_t)(b * kL + pos)) * kH + jj]);
    }
    return __ldcg(&g_nodeh[((size_t)(b * 128 + ref)) * kH + jj]);
}
__device__ __forceinline__ float c_of(int ref, int b, int jj) {
    if (ref < 0) return 0.0f;
    if (ref & REF_LEAF) {
        int pos = ref & 0xFFFF;
        return __ldcg(&g_cs[((size_t)(b * kL + pos)) * kH + jj]);
    }
    return __ldcg(&g_nodec[((size_t)(b * 128 + ref)) * kH + jj]);
}

// ---------------- generic tiled f32 GEMM: C[M,N] = A(MxK) @ B(NxK)^T (+bias) ----
// 256 threads, (BM/TM)x(BN/TN) must be 16x16. Grid-stride over tiles.
// A loads use __ldcg (cross-block producer), B via __ldg, C stores via __stcg.
template <int BM, int BN, int BK, int TM, int TN>
__device__ void gemmNT(const float *__restrict__ A, int lda, int M,
                       const float *__restrict__ Bm, int ldb,
                       int N, int K,
                       float *__restrict__ C, int ldc,
                       const float *__restrict__ bias1,
                       const float *__restrict__ bias2,
                       float *smem) {
    const int tid = threadIdx.x;
    const int ty = tid >> 4, tx = tid & 15;
    float *As = smem;                       // [BK][BM+4]
    float *Bs = smem + BK * (BM + 4);       // [BK][BN+4]
    const int tilesM = (M + BM - 1) / BM;
    const int tilesN = N / BN;
    for (int t = blockIdx.x; t < tilesM * tilesN; t += gridDim.x) {
        const int tm = t % tilesM, tn = t / tilesM;
        const int m0 = tm * BM, n0 = tn * BN;
        float acc[TM][TN];
#pragma unroll
        for (int i = 0; i < TM; i++)
#pragma unroll
            for (int j = 0; j < TN; j++) acc[i][j] = 0.0f;
        for (int k0 = 0; k0 < K; k0 += BK) {
#pragma unroll
            for (int idx = tid; idx < BM * BK; idx += 256) {
                int m = idx / BK, kk = idx - m * BK;
                int row = m0 + m, k = k0 + kk;
                float v = 0.0f;
                if (row < M && k < K) v = __ldcg(A + (size_t)row * lda + k);
                As[kk * (BM + 4) + m] = v;
            }
#pragma unroll
            for (int idx = tid; idx < BN * BK; idx += 256) {
                int n = idx / BK, kk = idx - n * BK;
                int k = k0 + kk;
                float v = 0.0f;
                if (k < K) v = __ldg(Bm + (size_t)(n0 + n) * ldb + k);
                Bs[kk * (BN + 4) + n] = v;
            }
            __syncthreads();
#pragma unroll
            for (int kk = 0; kk < BK; kk++) {
                float a[TM], bb[TN];
#pragma unroll
                for (int i = 0; i < TM; i++) a[i] = As[kk * (BM + 4) + ty * TM + i];
#pragma unroll
                for (int j = 0; j < TN; j++) bb[j] = Bs[kk * (BN + 4) + tx * TN + j];
#pragma unroll
                for (int i = 0; i < TM; i++)
#pragma unroll
                    for (int j = 0; j < TN; j++) acc[i][j] = fmaf(a[i], bb[j], acc[i][j]);
            }
            __syncthreads();
        }
#pragma unroll
        for (int i = 0; i < TM; i++) {
            int row = m0 + ty * TM + i;
            if (row < M) {
#pragma unroll
                for (int j = 0; j < TN; j++) {
                    int col = n0 + tx * TN + j;
                    float v = acc[i][j];
                    if (bias1) v += __ldg(bias1 + col);
                    if (bias2) v += __ldg(bias2 + col);
                    __stcg(C + (size_t)row * ldc + col, v);
                }
            }
        }
    }
}

// ---------------- tree structure kernel (1 block, 32 threads) ----------------
__global__ void tree_kernel(const int *__restrict__ words, const int *__restrict__ length) {
    int b = threadIdx.x;
    if (b < kB) {
        int df[kL];
        for (int l = 0; l < kL; l++) df[l] = words[b * kL + l] % 1000;
        int n = length[b];
        short ss[kL], se[kL], spos[kL];
        signed char sst[kL];
        int sleft[kL];
        int lvl[kL];
        int nn = 0;
        int root;
        if (n <= 0) {
            root = REF_NONE;
        } else if (n == 1) {
            root = REF_LEAF | 0;
        } else {
            int sp = 0;
            ss[0] = 0; se[0] = (short)n; sst[0] = 0; sp = 1;
            int ret = 0;
            bool returning = false;
            while (sp > 0) {
                int top = sp - 1;
                if (returning) {
                    if (sst[top] == 1) {
                        sleft[top] = ret; sst[top] = 2; returning = false;
                    } else {  // stage 3: ret is the right child -> complete node
                        int Lr = sleft[top], Rr = ret, x = spos[top];
                        int ll = (Lr >= 0 && !(Lr & REF_LEAF)) ? lvl[Lr] : 0;
                        int rl = (Rr >= 0 && !(Rr & REF_LEAF)) ? lvl[Rr] : 0;
                        lvl[nn] = 1 + (ll > rl ? ll : rl);
                        g_nodeL[b * 128 + nn] = Lr;
                        g_nodeR[b * 128 + nn] = Rr;
                        g_nodeX[b * 128 + nn] = x;
                        g_nodeLvl[b * 128 + nn] = lvl[nn];
                        ret = nn; nn++; sp--;
                        continue;  // still returning
                    }
                }
                if (sst[top] == 0) {
                    int s = ss[top], e = se[top];
                    int best = df[s], bp = s;
                    for (int k = s + 1; k < e; k++)
                        if (df[k] < best) { best = df[k]; bp = k; }  // first min == argmax score
                    spos[top] = (short)bp;
                    if (bp == s)        { sleft[top] = REF_NONE;     sst[top] = 2; }
                    else if (bp == s + 1) { sleft[top] = REF_LEAF | s; sst[top] = 2; }
                    else {
                        sst[top] = 1;
                        ss[sp] = (short)s; se[sp] = (short)bp; sst[sp] = 0; sp++;
                        continue;
                    }
                }
                if (sst[top] == 2) {
                    int rs = spos[top] + 1, e = se[top];
                    int Rr;
                    if (rs == e)          Rr = REF_NONE;
                    else if (rs + 1 == e) Rr = REF_LEAF | rs;
                    else {
                        sst[top] = 3;
                        ss[sp] = (short)rs; se[sp] = (short)e; sst[sp] = 0; sp++;
                        continue;
                    }
                    int Lr = sleft[top], x = spos[top];
                    int ll = (Lr >= 0 && !(Lr & REF_LEAF)) ? lvl[Lr] : 0;
                    int rl = (Rr >= 0 && !(Rr & REF_LEAF)) ? lvl[Rr] : 0;
                    lvl[nn] = 1 + (ll > rl ? ll : rl);
                    g_nodeL[b * 128 + nn] = Lr;
                    g_nodeR[b * 128 + nn] = Rr;
                    g_nodeX[b * 128 + nn] = x;
                    g_nodeLvl[b * 128 + nn] = lvl[nn];
                    ret = nn; nn++; sp--;
                    returning = true;
                }
            }
            root = ret;
        }
        g_root[b] = root;
        g_nNodes[b] = nn;
    }
    __syncthreads();
    if (threadIdx.x == 0) {
        int cnt[130];
        for (int i = 0; i < 130; i++) cnt[i] = 0;
        int mx = 0;
        for (int bb = 0; bb < kB; bb++) {
            int nn = g_nNodes[bb];
            for (int i = 0; i < nn; i++) {
                int lv = g_nodeLvl[bb * 128 + i];
                cnt[lv]++;
                if (lv > mx) mx = lv;
            }
        }
        int run = 0;
        for (int lv = 1; lv <= mx; lv++) { g_lvlOff[lv] = run; run += cnt[lv]; }
        g_lvlOff[mx + 1] = run;
        int pos[130];
        for (int lv = 1; lv <= mx; lv++) pos[lv] = g_lvlOff[lv];
        for (int bb = 0; bb < kB; bb++) {
            int nn = g_nNodes[bb];
            for (int i = 0; i < nn; i++) {
                int lv = g_nodeLvl[bb * 128 + i];
                g_lvlList[pos[lv]++] = (bb << 8) | i;
            }
        }
        g_maxLvl = mx;
    }
}

// ---------------- X precompute: g_X = emb @ W_ih^T + b_ih + b_hh ----------------
__global__ __launch_bounds__(256) void x_kernel(const float *__restrict__ emb,
                                                const float *__restrict__ Wih,
                                                const float *__restrict__ bih,
                                                const float *__restrict__ bhh) {
    __shared__ float smem[16 * 68 + 16 * 132];  // 3200 floats
    gemmNT<64, 128, 16, 4, 8>(emb, kD, kB * kL, Wih, kD, kH4, kD,
                              g_X, kH4, bih, bhh, smem);
}

// ---------------- persistent kernel: LSTM recurrence + tree compose + output ----
__global__ __launch_bounds__(256) void main_kernel(const float *__restrict__ Whh,
                                                   const float *__restrict__ Wcomp,
                                                   const float *__restrict__ bcomp,
                                                   float *__restrict__ out) {
    __shared__ float smem[16 * 68 + 16 * 132];  // big enough for both GEMM configs
    unsigned gen = *((volatile unsigned *)&g_barGen);
    const int tid = threadIdx.x;
    const int gsz = gridDim.x * 256;
    const int gtid = blockIdx.x * 256 + tid;

    // ---- LSTM t = 0 (h_prev = c_prev = 0; gates come only from X) ----
    for (int idx = gtid; idx < kB * kH; idx += gsz) {
        int b = idx >> 10, j = idx & 1023;
        const float *Xr = g_X + (size_t)(b * kL) * kH4;
        float gi = Xr[j], gf = Xr[kH + j], gg = Xr[2 * kH + j], go = Xr[3 * kH + j];
        (void)gf;  // c_prev = 0, forget term vanishes
        float c = sigm(gi) * tanhf(gg);
        float h = sigm(go) * tanhf(c);
        __stcg(&g_cs[(size_t)(b * kL) * kH + j], c);
        __stcg(&g_hs[(size_t)(b * kL) * kH + j], h);
    }
    gridBarrier(gen);

    // ---- LSTM t = 1..127 ----
    for (int t = 1; t < kL; t++) {
        gemmNT<32, 32, 32, 2, 2>(g_hs + (size_t)(t - 1) * kH, kL * kH, kB,
                                 Whh, kH, kH4, kH,
                                 g_gates, kH4, nullptr, nullptr, smem);
        gridBarrier(gen);
        for (int idx = gtid; idx < kB * kH; idx += gsz) {
            int b = idx >> 10, j = idx & 1023;
            const float *Xr = g_X + (size_t)(b * kL + t) * kH4;
            const float *Gr = g_gates + (size_t)b * kH4;
            float gi = __ldcg(Gr + j)          + Xr[j];
            float gf = __ldcg(Gr + kH + j)     + Xr[kH + j];
            float gg = __ldcg(Gr + 2 * kH + j) + Xr[2 * kH + j];
            float go = __ldcg(Gr + 3 * kH + j) + Xr[3 * kH + j];
            float cp = __ldcg(&g_cs[(size_t)(b * kL + t - 1) * kH + j]);
            float c = sigm(gf) * cp + sigm(gi) * tanhf(gg);
            float h = sigm(go) * tanhf(c);
            __stcg(&g_cs[(size_t)(b * kL + t) * kH + j], c);
            __stcg(&g_hs[(size_t)(b * kL + t) * kH + j], h);
        }
        gridBarrier(gen);
    }

    // ---- compose, level by level ----
    const int maxLvl = g_maxLvl;
    for (int lvl = 1; lvl <= maxLvl; lvl++) {
        const int off = g_lvlOff[lvl];
        const int cnt = g_lvlOff[lvl + 1] - off;

        // gather concat[h_l, h_x, h_r] into g_compIn
        for (int idx = gtid; idx < cnt * kH3; idx += gsz) {
            int i = idx / kH3, q = idx - i * kH3;
            int e = g_lvlList[off + i];
            int b = e >> 8, nd = e & 255;
            int seg = q >> 10, jj = q & 1023;
            float v;
            if (seg == 1) {
                int x = g_nodeX[b * 128 + nd];
                v = __ldcg(&g_hs[(size_t)(b * kL + x) * kH + jj]);
            } else {
                int r = (seg == 0) ? g_nodeL[b * 128 + nd] : g_nodeR[b * 128 + nd];
                v = h_of(r, b, jj);
            }
            __stcg(&g_compIn[(size_t)i * kH3 + q], v);
        }
        gridBarrier(gen);

        // batched GEMM: gates = compIn @ W_comp^T
        gemmNT<64, 128, 16, 4, 8>(g_compIn, kH3, cnt, Wcomp, kH3, kH6, kH3,
                                  g_gates, kH6, nullptr, nullptr, smem);
        gridBarrier(gen);

        // epilogue: gate nonlinearity + cell update
        for (int idx = gtid; idx < cnt * kH; idx += gsz) {
            int i = idx >> 10, jj = idx & 1023;
            int e = g_lvlList[off + i];
            int b = e >> 8, nd = e & 255;
            const float *g = g_gates + (size_t)i * kH6;
            float ai  = __ldcg(g + jj)            + __ldg(bcomp + jj);
            float afl = __ldcg(g + kH + jj)       + __ldg(bcomp + kH + jj);
            float afx = __ldcg(g + 2 * kH + jj)   + __ldg(bcomp + 2 * kH + jj);
            float afr = __ldcg(g + 3 * kH + jj)   + __ldg(bcomp + 3 * kH + jj);
            float au  = __ldcg(g + 4 * kH + jj)   + __ldg(bcomp + 4 * kH + jj);
            float ao  = __ldcg(g + 5 * kH + jj)   + __ldg(bcomp + 5 * kH + jj);
            int rl = g_nodeL[b * 128 + nd];
            int rr = g_nodeR[b * 128 + nd];
            int x  = g_nodeX[b * 128 + nd];
            float cl = c_of(rl, b, jj);
            float cr = c_of(rr, b, jj);
            float cx = __ldcg(&g_cs[(size_t)(b * kL + x) * kH + jj]);
            float c = sigm(ai) * tanhf(au) + sigm(afl) * cl + sigm(afx) * cx + sigm(afr) * cr;
            float h = sigm(ao) * tanhf(c);
            __stcg(&g_nodeh[(size_t)(b * 128 + nd) * kH + jj], h);
            __stcg(&g_nodec[(size_t)(b * 128 + nd) * kH + jj], c);
        }
        gridBarrier(gen);
    }

    // ---- output: h then c of each batch root ----
    for (int idx = gtid; idx < kB * kH; idx += gsz) {
        int b = idx >> 10, jj = idx & 1023;
        int r = g_root[b];
        out[idx]           = h_of(r, b, jj);
        out[kB * kH + idx] = c_of(r, b, jj);
    }
}

// ---------------- launch ----------------
extern "C" void kernel_launch(void *const *d_in, const int *in_sizes, int n_in,
                              void *d_out, int out_size) {
    (void)in_sizes; (void)n_in; (void)out_size;
    const float *emb   = (const float *)d_in[0];
    const float *Wih   = (const float *)d_in[1];
    const float *Whh   = (const float *)d_in[2];
    const float *bih   = (const float *)d_in[3];
    const float *bhh   = (const float *)d_in[4];
    const float *Wcomp = (const float *)d_in[5];
    const float *bcomp = (const float *)d_in[6];
    const int *words   = (const int *)d_in[7];
    const int *len     = (const int *)d_in[8];
    float *out = (float *)d_out;

    tree_kernel<<<1, 32>>>(words, len);
    x_kernel<<<2048, 256>>>(emb, Wih, bih, bhh);
    main_kernel<<<148, 256>>>(Whh, Wcomp, bcomp, out);
}

// round 6
// speedup vs baseline: 2.1301x; 1.9713x over previous
#include <cuda_runtime.h>
#include <cuda_bf16.h>
#include <stdint.h>

constexpr int kB  = 32;
constexpr int kL  = 128;
constexpr int kD  = 300;
constexpr int kH  = 1024;
constexpr int kH3 = 3 * kH;
constexpr int kH4 = 4 * kH;
constexpr int kH6 = 6 * kH;
constexpr int MAXM = 2048;
constexpr int GRID = 148;

#define REF_NONE  (-1)
#define REF_LEAF  0x40000000

// ---------------- device scratch ----------------
__device__ float g_X[(size_t)kB * kL * kH4];
__device__ float g_hs[(size_t)kB * kL * kH];
__device__ float g_cs[(size_t)kB * kL * kH];
__device__ float g_nodeh[(size_t)kB * 128 * kH];
__device__ float g_nodec[(size_t)kB * 128 * kH];
__device__ float g_compIn[(size_t)MAXM * kH3];
__device__ float g_gates[(size_t)MAXM * kH6];
__device__ float g_hT[2][kH * kB];     // quad-packed transpose: [(k>>2)*128 + b*4 + (k&3)]

__device__ int g_nodeL[kB * 128];
__device__ int g_nodeR[kB * 128];
__device__ int g_nodeX[kB * 128];
__device__ int g_nodeLvl[kB * 128];
__device__ int g_nNodes[kB];
__device__ int g_root[kB];
__device__ int g_lvlList[kB * 128];
__device__ int g_lvlOff[132];
__device__ int g_maxLvl;

__device__ unsigned g_barCount = 0;
__device__ unsigned g_barGen   = 0;

// ---------------- helpers ----------------
__device__ __forceinline__ float sigm(float x) { return 1.0f / (1.0f + expf(-x)); }

__device__ __forceinline__ void gridBarrier(unsigned &gen) {
    __syncthreads();
    if (threadIdx.x == 0) {
        __threadfence();
        if (atomicAdd(&g_barCount, 1u) == gridDim.x - 1u) {
            g_barCount = 0;
            __threadfence();
            atomicExch(&g_barGen, gen + 1u);
        } else {
            while (*((volatile unsigned *)&g_barGen) < gen + 1u) __nanosleep(32);
        }
    }
    gen++;
    __syncthreads();
}

__device__ __forceinline__ unsigned long long packdup(float x) {
    unsigned long long d; unsigned u = __float_as_uint(x);
    asm("mov.b64 %0, {%1, %1};" : "=l"(d) : "r"(u));
    return d;
}
__device__ __forceinline__ unsigned long long pack2(float x, float y) {
    unsigned long long d;
    asm("mov.b64 %0, {%1, %2};" : "=l"(d) : "r"(__float_as_uint(x)), "r"(__float_as_uint(y)));
    return d;
}
__device__ __forceinline__ void unpack2(unsigned long long d, float &x, float &y) {
    unsigned a, b;
    asm("mov.b64 {%0, %1}, %2;" : "=r"(a), "=r"(b) : "l"(d));
    x = __uint_as_float(a); y = __uint_as_float(b);
}
__device__ __forceinline__ void ffma2(unsigned long long &d, unsigned long long a,
                                      unsigned long long b) {
    asm("fma.rn.f32x2 %0, %1, %2, %0;" : "+l"(d) : "l"(a), "l"(b));
}

__device__ __forceinline__ float h_of(int ref, int b, int jj) {
    if (ref < 0) return 0.0f;
    if (ref & REF_LEAF) return __ldcg(&g_hs[((size_t)(b * kL + (ref & 0xFFFF))) * kH + jj]);
    return __ldcg(&g_nodeh[((size_t)(b * 128 + ref)) * kH + jj]);
}
__device__ __forceinline__ float c_of(int ref, int b, int jj) {
    if (ref < 0) return 0.0f;
    if (ref & REF_LEAF) return __ldcg(&g_cs[((size_t)(b * kL + (ref & 0xFFFF))) * kH + jj]);
    return __ldcg(&g_nodec[((size_t)(b * 128 + ref)) * kH + jj]);
}

// ---------------- f32x2 GEMM: C[M,N] = A(MxK) @ B(NxK)^T (+bias) ----------------
// BN=128, BK=16, 256 threads = 16(ty) x 16(tx); thread tile = TM x 8, TM = BM/16.
// Double-buffered smem: needs 2*16*(BM+4) + 2*16*132 floats.
template <int BM, bool ACG>
__device__ void gemm2(const float *__restrict__ A, int lda, int M,
                      const float *__restrict__ Bw, int ldb, int N, int K,
                      float *__restrict__ C, int ldc,
                      const float *__restrict__ bias1,
                      const float *__restrict__ bias2, float *sm) {
    constexpr int BN = 128, BK = 16;
    constexpr int TM = BM / 16;
    constexpr int NP = TM / 2;
    constexpr int ALD = BM + 4;
    float *As = sm;                    // [2][BK][ALD]
    float *Bs = sm + 2 * BK * ALD;     // [2][BK][132]
    const int tid = threadIdx.x;
    const int ty = tid >> 4, tx = tid & 15;
    const int tilesM = (M + BM - 1) / BM;
    const int tilesN = N / BN;
    const int nk = (K + BK - 1) / BK;

    for (int t = blockIdx.x; t < tilesM * tilesN; t += gridDim.x) {
        const int tm = t % tilesM, tn = t / tilesM;
        const int m0 = tm * BM, n0 = tn * BN;
        unsigned long long acc[NP][8];
#pragma unroll
        for (int p = 0; p < NP; p++)
#pragma unroll
            for (int j = 0; j < 8; j++) acc[p][j] = 0ULL;

        auto load = [&](int buf, int k0) {
#pragma unroll
            for (int i = 0; i < BM * BK / 256; i++) {
                int idx = tid + i * 256;
                int kk = idx & 15, m = idx >> 4;
                int row = m0 + m, k = k0 + kk;
                float v = 0.0f;
                if (row < M && k < K)
                    v = ACG ? __ldcg(A + (size_t)row * lda + k)
                            : __ldg(A + (size_t)row * lda + k);
                As[(buf * BK + kk) * ALD + m] = v;
            }
#pragma unroll
            for (int i = 0; i < 8; i++) {
                int idx = tid + i * 256;
                int kk = idx & 15, n = idx >> 4;
                int k = k0 + kk;
                float v = (k < K) ? __ldg(Bw + (size_t)(n0 + n) * ldb + k) : 0.0f;
                Bs[(buf * BK + kk) * 132 + n] = v;
            }
        };

        load(0, 0);
        __syncthreads();
        for (int kt = 0; kt < nk; kt++) {
            int buf = kt & 1;
            if (kt + 1 < nk) load(buf ^ 1, (kt + 1) * BK);
#pragma unroll
            for (int kk = 0; kk < BK; kk++) {
                const float *Ar = &As[(buf * BK + kk) * ALD + ty * TM];
                unsigned long long a2[NP];
#pragma unroll
                for (int p = 0; p < NP; p++)
                    a2[p] = *(const unsigned long long *)(Ar + 2 * p);
                const float4 *Br = (const float4 *)&Bs[(buf * BK + kk) * 132 + tx * 8];
                float4 b0 = Br[0], b1 = Br[1];
                unsigned long long bd[8];
                bd[0] = packdup(b0.x); bd[1] = packdup(b0.y);
                bd[2] = packdup(b0.z); bd[3] = packdup(b0.w);
                bd[4] = packdup(b1.x); bd[5] = packdup(b1.y);
                bd[6] = packdup(b1.z); bd[7] = packdup(b1.w);
#pragma unroll
                for (int p = 0; p < NP; p++)
#pragma unroll
                    for (int j = 0; j < 8; j++) ffma2(acc[p][j], a2[p], bd[j]);
            }
            __syncthreads();
        }
#pragma unroll
        for (int p = 0; p < NP; p++) {
            int r = m0 + ty * TM + 2 * p;
#pragma unroll
            for (int j = 0; j < 8; j++) {
                float x, y; unpack2(acc[p][j], x, y);
                int col = n0 + tx * 8 + j;
                float bv = 0.0f;
                if (bias1) bv += __ldg(bias1 + col);
                if (bias2) bv += __ldg(bias2 + col);
                if (r < M)     __stcg(C + (size_t)r * ldc + col, x + bv);
                if (r + 1 < M) __stcg(C + (size_t)(r + 1) * ldc + col, y + bv);
            }
        }
    }
}

// ---------------- tree kernel: warp per batch ----------------
__global__ __launch_bounds__(1024) void tree_kernel(const int *__restrict__ words,
                                                    const int *__restrict__ length) {
    int wid = threadIdx.x >> 5, lane = threadIdx.x & 31;
    if (wid < kB) {
        int b = wid;
        int dfv[4];
#pragma unroll
        for (int i = 0; i < 4; i++) dfv[i] = words[b * kL + lane + 32 * i] % 1000;
        int n = length[b];

        auto argminSeg = [&](int s, int e) -> int {
            int best = 0x7FFFFFFF;
#pragma unroll
            for (int i = 0; i < 4; i++) {
                int p = lane + 32 * i;
                if (p >= s && p < e) {
                    int pk = (dfv[i] << 7) | p;
                    if (pk < best) best = pk;
                }
            }
#pragma unroll
            for (int o = 16; o; o >>= 1) {
                int ot = __shfl_xor_sync(0xffffffffu, best, o);
                if (ot < best) best = ot;
            }
            return best & 127;
        };

        short ss[kL], se[kL], spos[kL];
        signed char sst[kL];
        int sleft[kL], lvl[kL];
        int nn = 0, root;
        if (n <= 0) root = REF_NONE;
        else if (n == 1) root = REF_LEAF | 0;
        else {
            int sp = 0;
            ss[0] = 0; se[0] = (short)n; sst[0] = 0; sp = 1;
            int ret = 0;
            bool returning = false;
            while (sp > 0) {
                int top = sp - 1;
                if (returning) {
                    if (sst[top] == 1) {
                        sleft[top] = ret; sst[top] = 2; returning = false;
                    } else {
                        int Lr = sleft[top], Rr = ret, x = spos[top];
                        int ll = (Lr >= 0 && !(Lr & REF_LEAF)) ? lvl[Lr] : 0;
                        int rl = (Rr >= 0 && !(Rr & REF_LEAF)) ? lvl[Rr] : 0;
                        lvl[nn] = 1 + (ll > rl ? ll : rl);
                        if (lane == 0) {
                            g_nodeL[b * 128 + nn] = Lr;
                            g_nodeR[b * 128 + nn] = Rr;
                            g_nodeX[b * 128 + nn] = x;
                            g_nodeLvl[b * 128 + nn] = lvl[nn];
                        }
                        ret = nn; nn++; sp--;
                        continue;
                    }
                }
                if (sst[top] == 0) {
                    int s = ss[top], e = se[top];
                    int bp = argminSeg(s, e);
                    spos[top] = (short)bp;
                    if (bp == s)          { sleft[top] = REF_NONE;     sst[top] = 2; }
                    else if (bp == s + 1) { sleft[top] = REF_LEAF | s; sst[top] = 2; }
                    else {
                        sst[top] = 1;
                        ss[sp] = (short)s; se[sp] = (short)bp; sst[sp] = 0; sp++;
                        continue;
                    }
                }
                if (sst[top] == 2) {
                    int rs = spos[top] + 1, e = se[top];
                    int Rr;
                    if (rs == e)          Rr = REF_NONE;
                    else if (rs + 1 == e) Rr = REF_LEAF | rs;
                    else {
                        sst[top] = 3;
                        ss[sp] = (short)rs; se[sp] = (short)e; sst[sp] = 0; sp++;
                        continue;
                    }
                    int Lr = sleft[top], x = spos[top];
                    int ll = (Lr >= 0 && !(Lr & REF_LEAF)) ? lvl[Lr] : 0;
                    int rl = (Rr >= 0 && !(Rr & REF_LEAF)) ? lvl[Rr] : 0;
                    lvl[nn] = 1 + (ll > rl ? ll : rl);
                    if (lane == 0) {
                        g_nodeL[b * 128 + nn] = Lr;
                        g_nodeR[b * 128 + nn] = Rr;
                        g_nodeX[b * 128 + nn] = x;
                        g_nodeLvl[b * 128 + nn] = lvl[nn];
                    }
                    ret = nn; nn++; sp--;
                    returning = true;
                }
            }
            root = ret;
        }
        if (lane == 0) { g_root[b] = root; g_nNodes[b] = nn; }
    }
    __syncthreads();
    if (threadIdx.x == 0) {
        int cnt[130];
        for (int i = 0; i < 130; i++) cnt[i] = 0;
        int mx = 0;
        for (int bb = 0; bb < kB; bb++) {
            int nn = g_nNodes[bb];
            for (int i = 0; i < nn; i++) {
                int lv = g_nodeLvl[bb * 128 + i];
                cnt[lv]++;
                if (lv > mx) mx = lv;
            }
        }
        int run = 0;
        for (int lv = 1; lv <= mx; lv++) { g_lvlOff[lv] = run; run += cnt[lv]; }
        g_lvlOff[mx + 1] = run;
        int pos[130];
        for (int lv = 1; lv <= mx; lv++) pos[lv] = g_lvlOff[lv];
        for (int bb = 0; bb < kB; bb++) {
            int nn = g_nNodes[bb];
            for (int i = 0; i < nn; i++) {
                int lv = g_nodeLvl[bb * 128 + i];
                g_lvlList[pos[lv]++] = (bb << 8) | i;
            }
        }
        g_maxLvl = mx;
    }
}

// ---------------- X precompute ----------------
__global__ __launch_bounds__(256) void x_kernel(const float *__restrict__ emb,
                                                const float *__restrict__ Wih,
                                                const float *__restrict__ bih,
                                                const float *__restrict__ bhh) {
    extern __shared__ float sm[];
    gemm2<128, false>(emb, kD, kB * kL, Wih, kD, kH4, kD, g_X, kH4, bih, bhh, sm);
}

// ---------------- persistent kernel: LSTM + compose + output ----------------
__global__ __launch_bounds__(256, 1) void main_kernel(const float *__restrict__ Whh,
                                                      const float *__restrict__ Wcomp,
                                                      const float *__restrict__ bcomp,
                                                      float *__restrict__ out) {
    extern __shared__ float sm[];
    unsigned gen = *((volatile unsigned *)&g_barGen);
    const int tid = threadIdx.x;
    const int gtid = blockIdx.x * 256 + tid;
    const int gsz = gridDim.x * 256;
    const int bk = blockIdx.x;

    // ======== Phase 1: weight-stationary LSTM ========
    // block bk owns columns j = bk*7 + s (s < nj); W slice in smem: [(s*4+g)*1024 + k]
    int nj = 1024 - bk * 7;
    if (nj > 7) nj = 7;
    if (nj < 0) nj = 0;
    for (int idx = tid; idx < nj * 4096; idx += 256)
        sm[idx] = __ldg(&Whh[((size_t)((idx >> 10) & 3) * kH + bk * 7 + (idx >> 12)) * kH
                             + (idx & 1023)]);
    __syncthreads();

    const int s = tid >> 5, b = tid & 31;
    const bool active = (s < nj);
    const int j = bk * 7 + s;
    const float *Ws = sm + s * 4096;
    float cprev = 0.0f;

    for (int t = 0; t < kL; t++) {
        float av[4] = {0.f, 0.f, 0.f, 0.f};
        if (active) {
            if (t > 0) {
                unsigned long long accp[4] = {0ULL, 0ULL, 0ULL, 0ULL};
                const float *hTp = (const float *)g_hT[(t - 1) & 1];
#pragma unroll 4
                for (int kq = 0; kq < 256; kq++) {
                    float4 h4 = __ldcg((const float4 *)(hTp + kq * 128 + b * 4));
                    unsigned long long alo = pack2(h4.x, h4.y);
                    unsigned long long ahi = pack2(h4.z, h4.w);
#pragma unroll
                    for (int g = 0; g < 4; g++) {
                        ulonglong2 w = *(const ulonglong2 *)(Ws + g * 1024 + kq * 4);
                        ffma2(accp[g], alo, w.x);
                        ffma2(accp[g], ahi, w.y);
                    }
                }
#pragma unroll
                for (int g = 0; g < 4; g++) {
                    float x, y; unpack2(accp[g], x, y);
                    av[g] = x + y;
                }
            }
            const float *Xr = g_X + ((size_t)(b * kL + t)) * kH4;
            float gi = av[0] + __ldg(Xr + j);
            float gf = av[1] + __ldg(Xr + kH + j);
            float gg = av[2] + __ldg(Xr + 2 * kH + j);
            float go = av[3] + __ldg(Xr + 3 * kH + j);
            float c = sigm(gf) * cprev + sigm(gi) * tanhf(gg);
            float h = sigm(go) * tanhf(c);
            cprev = c;
            __stcg(&g_hs[((size_t)(b * kL + t)) * kH + j], h);
            __stcg(&g_cs[((size_t)(b * kL + t)) * kH + j], c);
            __stcg(&g_hT[t & 1][(j >> 2) * 128 + b * 4 + (j & 3)], h);
        }
        gridBarrier(gen);
    }

    // ======== Phase 2: compose, level by level ========
    const int maxLvl = g_maxLvl;
    for (int lvl = 1; lvl <= maxLvl; lvl++) {
        const int off = g_lvlOff[lvl];
        const int cnt = g_lvlOff[lvl + 1] - off;

        // gather [h_l | h_x | h_r]
        for (int idx = gtid; idx < cnt * kH3; idx += gsz) {
            int i = idx / kH3, q = idx - i * kH3;
            int e = g_lvlList[off + i];
            int bb = e >> 8, nd = e & 255;
            int seg = q >> 10, jj = q & 1023;
            float v;
            if (seg == 1) {
                int x = g_nodeX[bb * 128 + nd];
                v = __ldcg(&g_hs[(size_t)(bb * kL + x) * kH + jj]);
            } else {
                int r = (seg == 0) ? g_nodeL[bb * 128 + nd] : g_nodeR[bb * 128 + nd];
                v = h_of(r, bb, jj);
            }
            __stcg(&g_compIn[(size_t)i * kH3 + q], v);
        }
        gridBarrier(gen);

        if (cnt <= 32)
            gemm2<32, true>(g_compIn, kH3, cnt, Wcomp, kH3, kH6, kH3,
                            g_gates, kH6, nullptr, nullptr, sm);
        else if (cnt <= 64)
            gemm2<64, true>(g_compIn, kH3, cnt, Wcomp, kH3, kH6, kH3,
                            g_gates, kH6, nullptr, nullptr, sm);
        else
            gemm2<128, true>(g_compIn, kH3, cnt, Wcomp, kH3, kH6, kH3,
                             g_gates, kH6, nullptr, nullptr, sm);
        gridBarrier(gen);

        for (int idx = gtid; idx < cnt * kH; idx += gsz) {
            int i = idx >> 10, jj = idx & 1023;
            int e = g_lvlList[off + i];
            int bb = e >> 8, nd = e & 255;
            const float *g = g_gates + (size_t)i * kH6;
            float ai  = __ldcg(g + jj)          + __ldg(bcomp + jj);
            float afl = __ldcg(g + kH + jj)     + __ldg(bcomp + kH + jj);
            float afx = __ldcg(g + 2 * kH + jj) + __ldg(bcomp + 2 * kH + jj);
            float afr = __ldcg(g + 3 * kH + jj) + __ldg(bcomp + 3 * kH + jj);
            float au  = __ldcg(g + 4 * kH + jj) + __ldg(bcomp + 4 * kH + jj);
            float ao  = __ldcg(g + 5 * kH + jj) + __ldg(bcomp + 5 * kH + jj);
            int rl = g_nodeL[bb * 128 + nd];
            int rr = g_nodeR[bb * 128 + nd];
            int x  = g_nodeX[bb * 128 + nd];
            float cl = c_of(rl, bb, jj);
            float cr = c_of(rr, bb, jj);
            float cx = __ldcg(&g_cs[(size_t)(bb * kL + x) * kH + jj]);
            float c = sigm(ai) * tanhf(au) + sigm(afl) * cl + sigm(afx) * cx + sigm(afr) * cr;
            float h = sigm(ao) * tanhf(c);
            __stcg(&g_nodeh[(size_t)(bb * 128 + nd) * kH + jj], h);
            __stcg(&g_nodec[(size_t)(bb * 128 + nd) * kH + jj], c);
        }
        gridBarrier(gen);
    }

    // ======== Phase 3: output ========
    for (int idx = gtid; idx < kB * kH; idx += gsz) {
        int bb = idx >> 10, jj = idx & 1023;
        int r = g_root[bb];
        out[idx]           = h_of(r, bb, jj);
        out[kB * kH + idx] = c_of(r, bb, jj);
    }
}

// ---------------- launch ----------------
extern "C" void kernel_launch(void *const *d_in, const int *in_sizes, int n_in,
                              void *d_out, int out_size) {
    (void)in_sizes; (void)n_in; (void)out_size;
    const float *emb   = (const float *)d_in[0];
    const float *Wih   = (const float *)d_in[1];
    const float *Whh   = (const float *)d_in[2];
    const float *bih   = (const float *)d_in[3];
    const float *bhh   = (const float *)d_in[4];
    const float *Wcomp = (const float *)d_in[5];
    const float *bcomp = (const float *)d_in[6];
    const int *words   = (const int *)d_in[7];
    const int *len     = (const int *)d_in[8];
    float *out = (float *)d_out;

    // smem sizes: gemm2<128> = (2*16*132 + 2*16*132)*4 = 33792 B; LSTM W slice = 114688 B
    static bool attrDone = false;
    if (!attrDone) {
        cudaFuncSetAttribute(main_kernel, cudaFuncAttributeMaxDynamicSharedMemorySize, 114688);
        attrDone = true;
    }

    tree_kernel<<<1, 1024>>>(words, len);
    x_kernel<<<1024, 256, 33792>>>(emb, Wih, bih, bhh);
    main_kernel<<<GRID, 256, 114688>>>(Whh, Wcomp, bcomp, out);
}